// round 2
// baseline (speedup 1.0000x reference)
#include <cuda_runtime.h>

// SelfAttentionHead: out = softmax_causal((x@Wq^T)(x@Wk^T)^T * C^-0.5) @ (x@Wv^T)
// B=1024, T=128, C=384, HS=64, fp32.
// One CTA per batch, 256 threads. Fully fused; x read once from HBM.
// All GEMM accumulation uses packed fma.rn.f32x2 (2 FMA/lane/instr on sm_103a).

static constexpr int kT  = 128;
static constexpr int kC  = 384;
static constexpr int kHS = 64;
static constexpr int kCH = 32;               // c-chunk
static constexpr int kNCH = kC / kCH;        // 12

// shared memory layout (floats)
static constexpr int KT_LD  = 132;           // sKt[64][132]  (K transposed: [h][s])
static constexpr int Q_LD   = 68;            // sQ [128][68]
static constexpr int V_LD   = 68;            // sV [128][68]
static constexpr int X_LD   = 129;           // sX [32][129]  (x chunk transposed: [c][t])
static constexpr int S_LD   = 132;           // sS [128][132] (scores/probs)

static constexpr int OFF_KT = 0;
static constexpr int OFF_Q  = OFF_KT + kHS * KT_LD;            // 8448
static constexpr int OFF_V  = OFF_Q  + kT * Q_LD;              // 17152
static constexpr int OFF_U  = OFF_V  + kT * V_LD;              // 25856 (union region)
static constexpr int OFF_X  = OFF_U;                           // stage 1
static constexpr int OFF_W  = OFF_U + kCH * X_LD;              // stage 1: sW[3][32][64]
static constexpr int OFF_S  = OFF_U;                           // stage 2
static constexpr int SMEM_FLOATS = OFF_U + kT * S_LD;          // 42752 floats = 171008 B

// ---- packed f32x2 helpers ----------------------------------------------
__device__ __forceinline__ unsigned long long pk2(float a, float b) {
    unsigned long long u;
    asm("mov.b64 %0, {%1, %2};" : "=l"(u) : "f"(a), "f"(b));
    return u;
}
__device__ __forceinline__ void upk2(unsigned long long u, float& a, float& b) {
    asm("mov.b64 {%0, %1}, %2;" : "=f"(a), "=f"(b) : "l"(u));
}
__device__ __forceinline__ unsigned long long ffma2(unsigned long long a,
                                                    unsigned long long b,
                                                    unsigned long long c) {
    unsigned long long d;
    asm("fma.rn.f32x2 %0, %1, %2, %3;" : "=l"(d) : "l"(a), "l"(b), "l"(c));
    return d;
}

__global__ void __launch_bounds__(256, 1)
attn_head_kernel(const float* __restrict__ x,
                 const float* __restrict__ Wk,
                 const float* __restrict__ Wq,
                 const float* __restrict__ Wv,
                 float* __restrict__ out) {
    extern __shared__ float sm[];
    float* sKt = sm + OFF_KT;
    float* sQ  = sm + OFF_Q;
    float* sV  = sm + OFF_V;
    float* sX  = sm + OFF_X;
    float* sW  = sm + OFF_W;
    float* sS  = sm + OFF_S;

    const int b   = blockIdx.x;
    const int tid = threadIdx.x;
    const int tx  = tid & 15;    // 16
    const int ty  = tid >> 4;    // 16
    const float* xb = x + (size_t)b * (kT * kC);

    // ================= Stage 1: K,Q,V projections =================
    // acc[m][i][jp]: m = {K,Q,V}, i = t-row (ty*8+i), jp = h-pair (tx*4 + 2*jp)
    unsigned long long acc[3][8][2];
#pragma unroll
    for (int m = 0; m < 3; ++m)
#pragma unroll
        for (int i = 0; i < 8; ++i) { acc[m][i][0] = 0ULL; acc[m][i][1] = 0ULL; }

    for (int cb = 0; cb < kNCH; ++cb) {
        const float* xc = xb + cb * kCH;
        // load x chunk transposed: sX[c][t]
#pragma unroll
        for (int r = 0; r < 4; ++r) {
            int idx = tid + 256 * r;                 // 0..1023
            int t = idx >> 3;
            int k = (idx & 7) * 4;
            float4 v = *(const float4*)(xc + t * kC + k);
            sX[(k + 0) * X_LD + t] = v.x;
            sX[(k + 1) * X_LD + t] = v.y;
            sX[(k + 2) * X_LD + t] = v.z;
            sX[(k + 3) * X_LD + t] = v.w;
        }
        // load W chunk transposed: sW[m][c][h]
#pragma unroll
        for (int r = 0; r < 6; ++r) {
            int idx = tid + 256 * r;                 // 0..1535
            int m = idx >> 9;
            int q = idx & 511;
            int h = q >> 3;
            int k = (q & 7) * 4;
            const float* Wm = (m == 0) ? Wk : ((m == 1) ? Wq : Wv);
            float4 v = *(const float4*)(Wm + h * kC + cb * kCH + k);
            float* wd = sW + (m * kCH + k) * kHS + h;
            wd[0 * kHS] = v.x;
            wd[1 * kHS] = v.y;
            wd[2 * kHS] = v.z;
            wd[3 * kHS] = v.w;
        }
        __syncthreads();

#pragma unroll 4
        for (int cc = 0; cc < kCH; ++cc) {
            unsigned long long xp[8];
#pragma unroll
            for (int i = 0; i < 8; ++i) {
                float xv = sX[cc * X_LD + ty * 8 + i];
                xp[i] = pk2(xv, xv);
            }
#pragma unroll
            for (int m = 0; m < 3; ++m) {
                float4 wv = *(const float4*)(sW + (m * kCH + cc) * kHS + tx * 4);
                unsigned long long w0 = pk2(wv.x, wv.y);
                unsigned long long w1 = pk2(wv.z, wv.w);
#pragma unroll
                for (int i = 0; i < 8; ++i) {
                    acc[m][i][0] = ffma2(xp[i], w0, acc[m][i][0]);
                    acc[m][i][1] = ffma2(xp[i], w1, acc[m][i][1]);
                }
            }
        }
        __syncthreads();
    }

    // epilogue: K transposed, Q/V row-major
#pragma unroll
    for (int i = 0; i < 8; ++i) {
        int t = ty * 8 + i;
        float a0, a1, a2, a3;
        upk2(acc[0][i][0], a0, a1);
        upk2(acc[0][i][1], a2, a3);
        sKt[(tx * 4 + 0) * KT_LD + t] = a0;
        sKt[(tx * 4 + 1) * KT_LD + t] = a1;
        sKt[(tx * 4 + 2) * KT_LD + t] = a2;
        sKt[(tx * 4 + 3) * KT_LD + t] = a3;
        float q0, q1, q2, q3;
        upk2(acc[1][i][0], q0, q1);
        upk2(acc[1][i][1], q2, q3);
        *(float4*)(sQ + t * Q_LD + tx * 4) = make_float4(q0, q1, q2, q3);
        float v0, v1, v2, v3;
        upk2(acc[2][i][0], v0, v1);
        upk2(acc[2][i][1], v2, v3);
        *(float4*)(sV + t * V_LD + tx * 4) = make_float4(v0, v1, v2, v3);
    }
    __syncthreads();

    // ================= Stage 2: scores = scale * Q @ K^T =================
    // thread tile: t = ty*8 + i (8 rows), s = tx*8 + 2*jp + {0,1} (8 cols)
    {
        unsigned long long sacc[8][4];
#pragma unroll
        for (int i = 0; i < 8; ++i)
#pragma unroll
            for (int jp = 0; jp < 4; ++jp) sacc[i][jp] = 0ULL;

#pragma unroll 2
        for (int h = 0; h < kHS; ++h) {
            unsigned long long qp[8];
#pragma unroll
            for (int i = 0; i < 8; ++i) {
                float qv = sQ[(ty * 8 + i) * Q_LD + h];
                qp[i] = pk2(qv, qv);
            }
            unsigned long long kt[4];
#pragma unroll
            for (int jp = 0; jp < 4; ++jp) {
                float2 kv = *(const float2*)(sKt + h * KT_LD + tx * 8 + jp * 2);
                kt[jp] = pk2(kv.x, kv.y);
            }
#pragma unroll
            for (int i = 0; i < 8; ++i)
#pragma unroll
                for (int jp = 0; jp < 4; ++jp)
                    sacc[i][jp] = ffma2(qp[i], kt[jp], sacc[i][jp]);
        }

        const float scale = 0.05103103630798288f;  // 384^-0.5
#pragma unroll
        for (int i = 0; i < 8; ++i) {
            int t = ty * 8 + i;
            float w0, w1, w2, w3, w4, w5, w6, w7;
            upk2(sacc[i][0], w0, w1);
            upk2(sacc[i][1], w2, w3);
            upk2(sacc[i][2], w4, w5);
            upk2(sacc[i][3], w6, w7);
            *(float4*)(sS + t * S_LD + tx * 8 + 0) =
                make_float4(w0 * scale, w1 * scale, w2 * scale, w3 * scale);
            *(float4*)(sS + t * S_LD + tx * 8 + 4) =
                make_float4(w4 * scale, w5 * scale, w6 * scale, w7 * scale);
        }
    }
    __syncthreads();

    // ================= Stage 3: causal softmax (one thread per row) =================
    if (tid < kT) {
        const int t = tid;
        float* row = sS + t * S_LD;
        float m = -1e30f;
        for (int s = 0; s <= t; ++s) m = fmaxf(m, row[s]);
        float sum = 0.f;
        for (int s = 0; s <= t; ++s) {
            float e = __expf(row[s] - m);
            row[s] = e;
            sum += e;
        }
        float inv = 1.0f / sum;
        for (int s = 0; s <= t; ++s) row[s] *= inv;
        for (int s = t + 1; s < kT; ++s) row[s] = 0.f;
    }
    __syncthreads();

    // ================= Stage 4: out = P @ V =================
    // thread tile: t = ty*8 + i (8 rows), h = tx*4 + 2*jp + {0,1}
    {
        unsigned long long oacc[8][2];
#pragma unroll
        for (int i = 0; i < 8; ++i) { oacc[i][0] = 0ULL; oacc[i][1] = 0ULL; }

#pragma unroll 2
        for (int s = 0; s < kT; ++s) {
            float4 vv = *(const float4*)(sV + s * V_LD + tx * 4);
            unsigned long long v0 = pk2(vv.x, vv.y);
            unsigned long long v1 = pk2(vv.z, vv.w);
#pragma unroll
            for (int i = 0; i < 8; ++i) {
                float p = sS[(ty * 8 + i) * S_LD + s];
                unsigned long long pp = pk2(p, p);
                oacc[i][0] = ffma2(pp, v0, oacc[i][0]);
                oacc[i][1] = ffma2(pp, v1, oacc[i][1]);
            }
        }

        float* ob = out + (size_t)b * (kT * kHS);
#pragma unroll
        for (int i = 0; i < 8; ++i) {
            int t = ty * 8 + i;
            float o0, o1, o2, o3;
            upk2(oacc[i][0], o0, o1);
            upk2(oacc[i][1], o2, o3);
            *(float4*)(ob + t * kHS + tx * 4) = make_float4(o0, o1, o2, o3);
        }
    }
}

extern "C" void kernel_launch(void* const* d_in, const int* in_sizes, int n_in,
                              void* d_out, int out_size) {
    const float* x  = (const float*)d_in[0];
    const float* Wk = (const float*)d_in[1];
    const float* Wq = (const float*)d_in[2];
    const float* Wv = (const float*)d_in[3];
    float* out = (float*)d_out;

    const int B = in_sizes[0] / (kT * kC);   // 1024
    const size_t smem = SMEM_FLOATS * sizeof(float);  // 171008 B

    cudaFuncSetAttribute(attn_head_kernel,
                         cudaFuncAttributeMaxDynamicSharedMemorySize, (int)smem);
    attn_head_kernel<<<B, 256, smem>>>(x, Wk, Wq, Wv, out);
}

// round 5
// speedup vs baseline: 2.5400x; 2.5400x over previous
#include <cuda_runtime.h>
#include <cstdint>

// Fused causal self-attention head, warp-level mma.sync tf32 (sm_80+ PTX path).
// B=1024, T=128, C=384, HS=64, fp32 in/out.
// One CTA per batch, 512 threads (16 warps), ~192KB dynamic smem.

static constexpr int kT   = 128;
static constexpr int kC   = 384;
static constexpr int kHS  = 64;
static constexpr int kCH  = 32;             // K-chunk
static constexpr int kNCH = kC / kCH;       // 12
static constexpr int kNW  = 192;            // combined N = 3*64 (Wk|Wq|Wv)

// smem word offsets
static constexpr int LD_KQV = 68;           // pad for conflict-free frags + float2 align
static constexpr int LD_XW  = 36;           // pad, 16B-aligned rows
static constexpr int LD_S   = 133;
static constexpr int W_K  = 0;
static constexpr int W_Q  = W_K + kT * LD_KQV;          // 8704
static constexpr int W_V  = W_Q + kT * LD_KQV;          // 17408
static constexpr int W_U  = W_V + kT * LD_KQV;          // 26112 (union region)
static constexpr int XBUF_W = kT  * LD_XW;              // 4608
static constexpr int WBUF_W = kNW * LD_XW;              // 6912
static constexpr int BUF_W  = XBUF_W + WBUF_W;          // 11520
static constexpr int SMEM_WORDS = W_U + 2 * BUF_W;      // 49152 words = 196608 B
static constexpr int SMEM_BYTES = SMEM_WORDS * 4;

// ---------------- helpers ----------------
__device__ __forceinline__ uint32_t f2tf(float f) {
    uint32_t r;
    asm("cvt.rna.tf32.f32 %0, %1;" : "=r"(r) : "f"(f));
    return r;
}
__device__ __forceinline__ void mma_tf32(float c[4], const uint32_t a[4],
                                         uint32_t b0, uint32_t b1) {
    asm volatile(
        "mma.sync.aligned.m16n8k8.row.col.f32.tf32.tf32.f32 "
        "{%0,%1,%2,%3}, {%4,%5,%6,%7}, {%8,%9}, {%0,%1,%2,%3};"
        : "+f"(c[0]), "+f"(c[1]), "+f"(c[2]), "+f"(c[3])
        : "r"(a[0]), "r"(a[1]), "r"(a[2]), "r"(a[3]), "r"(b0), "r"(b1));
}

// ---------------- kernel ----------------
__global__ void __launch_bounds__(512, 1)
attn_mma_kernel(const float* __restrict__ x,
                const float* __restrict__ Wk,
                const float* __restrict__ Wq,
                const float* __restrict__ Wv,
                float* __restrict__ out) {
    extern __shared__ uint32_t sm[];
    const int tid  = threadIdx.x;
    const int wid  = tid >> 5;
    const int lane = tid & 31;
    const int g4   = lane >> 2;      // group id 0..7
    const int t4   = lane & 3;       // thread in group 0..3
    const int wm   = wid & 7;        // m-tile (16 rows each)
    const int wn   = wid >> 3;       // n-split 0/1
    const int b    = blockIdx.x;
    const float* xb = x + (size_t)b * (kT * kC);

    // ===== Stage A: KQV = x @ [Wk|Wq|Wv]^T, K-chunked, reg-prefetch dbuf =====
    float4 xr[2], wr[3];
    // prefetch chunk 0
    {
        const int cbase = 0;
#pragma unroll
        for (int r = 0; r < 2; ++r) {
            int idx = tid + 512 * r, t = idx >> 3, f4 = idx & 7;
            xr[r] = *(const float4*)(xb + t * kC + cbase + f4 * 4);
        }
#pragma unroll
        for (int r = 0; r < 3; ++r) {
            int idx = tid + 512 * r, n = idx >> 3, f4 = idx & 7;
            const float* Wm = (n < 64) ? (Wk + n * kC)
                              : (n < 128) ? (Wq + (n - 64) * kC)
                                          : (Wv + (n - 128) * kC);
            wr[r] = *(const float4*)(Wm + cbase + f4 * 4);
        }
    }
    // store chunk 0 into buf 0
    {
        uint32_t* bx = sm + W_U;
        uint32_t* bw = bx + XBUF_W;
#pragma unroll
        for (int r = 0; r < 2; ++r) {
            int idx = tid + 512 * r, t = idx >> 3, f4 = idx & 7;
            *(uint4*)(bx + t * LD_XW + f4 * 4) =
                make_uint4(f2tf(xr[r].x), f2tf(xr[r].y), f2tf(xr[r].z), f2tf(xr[r].w));
        }
#pragma unroll
        for (int r = 0; r < 3; ++r) {
            int idx = tid + 512 * r, n = idx >> 3, f4 = idx & 7;
            *(uint4*)(bw + n * LD_XW + f4 * 4) =
                make_uint4(f2tf(wr[r].x), f2tf(wr[r].y), f2tf(wr[r].z), f2tf(wr[r].w));
        }
    }
    __syncthreads();

    float c[12][4];
#pragma unroll
    for (int t = 0; t < 12; ++t) { c[t][0] = c[t][1] = c[t][2] = c[t][3] = 0.f; }

    for (int cb = 0; cb < kNCH; ++cb) {
        const int p = cb & 1;
        // prefetch next chunk to regs
        if (cb + 1 < kNCH) {
            const int cbase = (cb + 1) * kCH;
#pragma unroll
            for (int r = 0; r < 2; ++r) {
                int idx = tid + 512 * r, t = idx >> 3, f4 = idx & 7;
                xr[r] = *(const float4*)(xb + t * kC + cbase + f4 * 4);
            }
#pragma unroll
            for (int r = 0; r < 3; ++r) {
                int idx = tid + 512 * r, n = idx >> 3, f4 = idx & 7;
                const float* Wm = (n < 64) ? (Wk + n * kC)
                                  : (n < 128) ? (Wq + (n - 64) * kC)
                                              : (Wv + (n - 128) * kC);
                wr[r] = *(const float4*)(Wm + cbase + f4 * 4);
            }
        }
        // compute on buffer p
        {
            const uint32_t* bx = sm + W_U + p * BUF_W;
            const uint32_t* bw = bx + XBUF_W;
            const int row0 = wm * 16 + g4;
#pragma unroll
            for (int kk = 0; kk < 4; ++kk) {
                uint32_t a[4];
                a[0] = bx[(row0    ) * LD_XW + kk * 8 + t4];
                a[1] = bx[(row0 + 8) * LD_XW + kk * 8 + t4];
                a[2] = bx[(row0    ) * LD_XW + kk * 8 + t4 + 4];
                a[3] = bx[(row0 + 8) * LD_XW + kk * 8 + t4 + 4];
#pragma unroll
                for (int t = 0; t < 12; ++t) {
                    int n = wn * 96 + t * 8 + g4;
                    uint32_t b0 = bw[n * LD_XW + kk * 8 + t4];
                    uint32_t b1 = bw[n * LD_XW + kk * 8 + t4 + 4];
                    mma_tf32(c[t], a, b0, b1);
                }
            }
        }
        // store prefetched chunk to other buffer
        if (cb + 1 < kNCH) {
            uint32_t* bx = sm + W_U + (p ^ 1) * BUF_W;
            uint32_t* bw = bx + XBUF_W;
#pragma unroll
            for (int r = 0; r < 2; ++r) {
                int idx = tid + 512 * r, t = idx >> 3, f4 = idx & 7;
                *(uint4*)(bx + t * LD_XW + f4 * 4) =
                    make_uint4(f2tf(xr[r].x), f2tf(xr[r].y), f2tf(xr[r].z), f2tf(xr[r].w));
            }
#pragma unroll
            for (int r = 0; r < 3; ++r) {
                int idx = tid + 512 * r, n = idx >> 3, f4 = idx & 7;
                *(uint4*)(bw + n * LD_XW + f4 * 4) =
                    make_uint4(f2tf(wr[r].x), f2tf(wr[r].y), f2tf(wr[r].z), f2tf(wr[r].w));
            }
        }
        __syncthreads();
    }

    // epilogue: scatter K/Q/V (rounded to tf32)
    {
        const int r0 = wm * 16 + g4, r1 = r0 + 8;
#pragma unroll
        for (int t = 0; t < 12; ++t) {
            int gc  = wn * 96 + t * 8 + 2 * t4;
            int m   = gc >> 6;
            int col = gc & 63;
            uint32_t* dst = sm + (m == 0 ? W_K : (m == 1 ? W_Q : W_V));
            dst[r0 * LD_KQV + col    ] = f2tf(c[t][0]);
            dst[r0 * LD_KQV + col + 1] = f2tf(c[t][1]);
            dst[r1 * LD_KQV + col    ] = f2tf(c[t][2]);
            dst[r1 * LD_KQV + col + 1] = f2tf(c[t][3]);
        }
    }
    __syncthreads();

    // ===== Stage B: S = scale * Q @ K^T  (M=128,N=128,K=64) =====
    {
        float cs[8][4];
#pragma unroll
        for (int t = 0; t < 8; ++t) { cs[t][0] = cs[t][1] = cs[t][2] = cs[t][3] = 0.f; }
        const uint32_t* sQ = sm + W_Q;
        const uint32_t* sK = sm + W_K;
        const int row0 = wm * 16 + g4;
#pragma unroll
        for (int kk = 0; kk < 8; ++kk) {
            uint32_t a[4];
            a[0] = sQ[(row0    ) * LD_KQV + kk * 8 + t4];
            a[1] = sQ[(row0 + 8) * LD_KQV + kk * 8 + t4];
            a[2] = sQ[(row0    ) * LD_KQV + kk * 8 + t4 + 4];
            a[3] = sQ[(row0 + 8) * LD_KQV + kk * 8 + t4 + 4];
#pragma unroll
            for (int t = 0; t < 8; ++t) {
                int n = wn * 64 + t * 8 + g4;
                uint32_t b0 = sK[n * LD_KQV + kk * 8 + t4];
                uint32_t b1 = sK[n * LD_KQV + kk * 8 + t4 + 4];
                mma_tf32(cs[t], a, b0, b1);
            }
        }
        const float scale = 0.05103103630798288f;    // 384^-0.5
        float* sS = (float*)(sm + W_U);
        const int r0 = wm * 16 + g4, r1 = r0 + 8;
#pragma unroll
        for (int t = 0; t < 8; ++t) {
            int col = wn * 64 + t * 8 + 2 * t4;
            sS[r0 * LD_S + col    ] = cs[t][0] * scale;
            sS[r0 * LD_S + col + 1] = cs[t][1] * scale;
            sS[r1 * LD_S + col    ] = cs[t][2] * scale;
            sS[r1 * LD_S + col + 1] = cs[t][3] * scale;
        }
    }
    __syncthreads();

    // ===== Stage C: causal softmax, P stored as tf32 bits =====
    if (tid < kT) {
        const int t = tid;
        float* rowf = (float*)(sm + W_U) + t * LD_S;
        uint32_t* rowu = sm + W_U + t * LD_S;
        float m = -1e30f;
        for (int s = 0; s <= t; ++s) m = fmaxf(m, rowf[s]);
        float sum = 0.f;
        for (int s = 0; s <= t; ++s) {
            float e = __expf(rowf[s] - m);
            rowf[s] = e;
            sum += e;
        }
        float inv = 1.0f / sum;
        for (int s = 0; s <= t; ++s) rowu[s] = f2tf(rowf[s] * inv);
        for (int s = t + 1; s < kT; ++s) rowu[s] = 0u;
    }
    __syncthreads();

    // ===== Stage D: out = P @ V  (M=128,N=64,K=128) =====
    {
        float co[4][4];
#pragma unroll
        for (int t = 0; t < 4; ++t) { co[t][0] = co[t][1] = co[t][2] = co[t][3] = 0.f; }
        const uint32_t* sP = sm + W_U;
        const uint32_t* sV = sm + W_V;
        const int row0 = wm * 16 + g4;
#pragma unroll
        for (int kk = 0; kk < 16; ++kk) {
            uint32_t a[4];
            a[0] = sP[(row0    ) * LD_S + kk * 8 + t4];
            a[1] = sP[(row0 + 8) * LD_S + kk * 8 + t4];
            a[2] = sP[(row0    ) * LD_S + kk * 8 + t4 + 4];
            a[3] = sP[(row0 + 8) * LD_S + kk * 8 + t4 + 4];
#pragma unroll
            for (int t = 0; t < 4; ++t) {
                int n = wn * 32 + t * 8 + g4;
                uint32_t b0 = sV[(kk * 8 + t4    ) * LD_KQV + n];
                uint32_t b1 = sV[(kk * 8 + t4 + 4) * LD_KQV + n];
                mma_tf32(co[t], a, b0, b1);
            }
        }
        float* ob = out + (size_t)b * (kT * kHS);
        const int r0 = wm * 16 + g4, r1 = r0 + 8;
#pragma unroll
        for (int t = 0; t < 4; ++t) {
            int col = wn * 32 + t * 8 + 2 * t4;
            *(float2*)(ob + r0 * kHS + col) = make_float2(co[t][0], co[t][1]);
            *(float2*)(ob + r1 * kHS + col) = make_float2(co[t][2], co[t][3]);
        }
    }
}

extern "C" void kernel_launch(void* const* d_in, const int* in_sizes, int n_in,
                              void* d_out, int out_size) {
    const float* x  = (const float*)d_in[0];
    const float* Wk = (const float*)d_in[1];
    const float* Wq = (const float*)d_in[2];
    const float* Wv = (const float*)d_in[3];
    float* out = (float*)d_out;

    const int B = in_sizes[0] / (kT * kC);   // 1024
    cudaFuncSetAttribute(attn_mma_kernel,
                         cudaFuncAttributeMaxDynamicSharedMemorySize, SMEM_BYTES);
    attn_mma_kernel<<<B, 512, SMEM_BYTES>>>(x, Wk, Wq, Wv, out);
}

// round 6
// speedup vs baseline: 4.0752x; 1.6044x over previous
#include <cuda_runtime.h>
#include <cuda_fp16.h>
#include <cstdint>

// Fused causal self-attention head, mma.sync m16n8k16 fp16 (fp32 accum), sm_103a.
// B=1024, T=128, C=384, HS=64, fp32 in/out.
// One CTA per batch, 512 threads (16 warps), ~154KB dynamic smem.

static constexpr int kT   = 128;
static constexpr int kC   = 384;
static constexpr int kHS  = 64;
static constexpr int kCH  = 32;             // K-chunk (floats)
static constexpr int kNCH = kC / kCH;       // 12
static constexpr int kNW  = 192;            // combined N = 3*64 (Wk|Wq|Wv)

// strides in 4B words (half2 units for fp16 regions)
static constexpr int LDXW = 20;             // x/w staging rows: 16 half2 data + 4 pad
static constexpr int LDH  = 36;             // K/Q rows: 32 half2 + 4 pad
static constexpr int LDVT = 68;             // Vt rows: 64 half2 + 4 pad
static constexpr int LDS_ = 134;            // S rows (fp32 words)
static constexpr int LDP  = 68;             // P rows: 64 half2 + 4 pad

static constexpr int W_K  = 0;
static constexpr int W_Q  = W_K + kT * LDH;         // 4608
static constexpr int W_VT = W_Q + kT * LDH;         // 9216
static constexpr int W_U  = W_VT + kHS * LDVT;      // 13568
static constexpr int XBUF_W = kT  * LDXW;           // 2560
static constexpr int WBUF_W = kNW * LDXW;           // 3840
static constexpr int BUF_W  = XBUF_W + WBUF_W;      // 6400 (2 bufs alias S/P region)
static constexpr int W_S  = W_U;                    // fp32 scores
static constexpr int W_P  = W_S + kT * LDS_;        // 30720
static constexpr int SMEM_WORDS = W_P + kT * LDP;   // 39424
static constexpr int SMEM_BYTES = SMEM_WORDS * 4;   // 157696

// ---------------- helpers ----------------
__device__ __forceinline__ uint32_t pkh2(float a, float b) {
    __half2 h = __floats2half2_rn(a, b);
    return *(uint32_t*)&h;
}
__device__ __forceinline__ void mma_f16(float c[4], const uint32_t a[4],
                                        uint32_t b0, uint32_t b1) {
    asm volatile(
        "mma.sync.aligned.m16n8k16.row.col.f32.f16.f16.f32 "
        "{%0,%1,%2,%3}, {%4,%5,%6,%7}, {%8,%9}, {%0,%1,%2,%3};"
        : "+f"(c[0]), "+f"(c[1]), "+f"(c[2]), "+f"(c[3])
        : "r"(a[0]), "r"(a[1]), "r"(a[2]), "r"(a[3]), "r"(b0), "r"(b1));
}

// ---------------- kernel ----------------
__global__ void __launch_bounds__(512, 1)
attn_mma_kernel(const float* __restrict__ x,
                const float* __restrict__ Wk,
                const float* __restrict__ Wq,
                const float* __restrict__ Wv,
                float* __restrict__ out) {
    extern __shared__ uint32_t sm[];
    const int tid  = threadIdx.x;
    const int wid  = tid >> 5;
    const int lane = tid & 31;
    const int g4   = lane >> 2;      // 0..7
    const int t4   = lane & 3;       // 0..3
    const int wm   = wid & 3;        // m-group (32 rows)
    const int wn   = wid >> 2;       // n-group
    const int b    = blockIdx.x;
    const float* xb = x + (size_t)b * (kT * kC);

    // ===== Stage A: KQV = x @ [Wk|Wq|Wv]^T, K-chunked, reg-prefetch dbuf =====
    float4 xr[2], wr[3];
    {
#pragma unroll
        for (int r = 0; r < 2; ++r) {
            int idx = tid + 512 * r, t = idx >> 3, f4 = idx & 7;
            xr[r] = *(const float4*)(xb + t * kC + f4 * 4);
        }
#pragma unroll
        for (int r = 0; r < 3; ++r) {
            int idx = tid + 512 * r, n = idx >> 3, f4 = idx & 7;
            const float* Wm = (n < 64) ? (Wk + n * kC)
                              : (n < 128) ? (Wq + (n - 64) * kC)
                                          : (Wv + (n - 128) * kC);
            wr[r] = *(const float4*)(Wm + f4 * 4);
        }
    }
    {
        uint32_t* bx = sm + W_U;
        uint32_t* bw = bx + XBUF_W;
#pragma unroll
        for (int r = 0; r < 2; ++r) {
            int idx = tid + 512 * r, t = idx >> 3, f4 = idx & 7;
            *(uint2*)(bx + t * LDXW + f4 * 2) =
                make_uint2(pkh2(xr[r].x, xr[r].y), pkh2(xr[r].z, xr[r].w));
        }
#pragma unroll
        for (int r = 0; r < 3; ++r) {
            int idx = tid + 512 * r, n = idx >> 3, f4 = idx & 7;
            *(uint2*)(bw + n * LDXW + f4 * 2) =
                make_uint2(pkh2(wr[r].x, wr[r].y), pkh2(wr[r].z, wr[r].w));
        }
    }
    __syncthreads();

    float c[2][6][4];
#pragma unroll
    for (int mt = 0; mt < 2; ++mt)
#pragma unroll
        for (int nt = 0; nt < 6; ++nt)
#pragma unroll
            for (int j = 0; j < 4; ++j) c[mt][nt][j] = 0.f;

    for (int cb = 0; cb < kNCH; ++cb) {
        const int p = cb & 1;
        if (cb + 1 < kNCH) {
            const int cbase = (cb + 1) * kCH;
#pragma unroll
            for (int r = 0; r < 2; ++r) {
                int idx = tid + 512 * r, t = idx >> 3, f4 = idx & 7;
                xr[r] = *(const float4*)(xb + t * kC + cbase + f4 * 4);
            }
#pragma unroll
            for (int r = 0; r < 3; ++r) {
                int idx = tid + 512 * r, n = idx >> 3, f4 = idx & 7;
                const float* Wm = (n < 64) ? (Wk + n * kC)
                                  : (n < 128) ? (Wq + (n - 64) * kC)
                                              : (Wv + (n - 128) * kC);
                wr[r] = *(const float4*)(Wm + cbase + f4 * 4);
            }
        }
        {
            const uint32_t* bx = sm + W_U + p * BUF_W;
            const uint32_t* bw = bx + XBUF_W;
#pragma unroll
            for (int kk = 0; kk < 2; ++kk) {
                uint32_t a[2][4];
#pragma unroll
                for (int mt = 0; mt < 2; ++mt) {
                    int r0 = wm * 32 + mt * 16 + g4;
                    a[mt][0] = bx[(r0    ) * LDXW + kk * 8 + t4];
                    a[mt][1] = bx[(r0 + 8) * LDXW + kk * 8 + t4];
                    a[mt][2] = bx[(r0    ) * LDXW + kk * 8 + t4 + 4];
                    a[mt][3] = bx[(r0 + 8) * LDXW + kk * 8 + t4 + 4];
                }
#pragma unroll
                for (int nt = 0; nt < 6; ++nt) {
                    int n = wn * 48 + nt * 8 + g4;
                    uint32_t b0 = bw[n * LDXW + kk * 8 + t4];
                    uint32_t b1 = bw[n * LDXW + kk * 8 + t4 + 4];
                    mma_f16(c[0][nt], a[0], b0, b1);
                    mma_f16(c[1][nt], a[1], b0, b1);
                }
            }
        }
        if (cb + 1 < kNCH) {
            uint32_t* bx = sm + W_U + (p ^ 1) * BUF_W;
            uint32_t* bw = bx + XBUF_W;
#pragma unroll
            for (int r = 0; r < 2; ++r) {
                int idx = tid + 512 * r, t = idx >> 3, f4 = idx & 7;
                *(uint2*)(bx + t * LDXW + f4 * 2) =
                    make_uint2(pkh2(xr[r].x, xr[r].y), pkh2(xr[r].z, xr[r].w));
            }
#pragma unroll
            for (int r = 0; r < 3; ++r) {
                int idx = tid + 512 * r, n = idx >> 3, f4 = idx & 7;
                *(uint2*)(bw + n * LDXW + f4 * 2) =
                    make_uint2(pkh2(wr[r].x, wr[r].y), pkh2(wr[r].z, wr[r].w));
            }
        }
        __syncthreads();
    }

    // epilogue: K,Q row-major half2 [t][h]; V transposed half [h][s]
    {
        __half* vh = (__half*)(sm + W_VT);
#pragma unroll
        for (int mt = 0; mt < 2; ++mt) {
            int r0 = wm * 32 + mt * 16 + g4, r1 = r0 + 8;
#pragma unroll
            for (int nt = 0; nt < 6; ++nt) {
                int gc = wn * 48 + nt * 8 + 2 * t4;
                int m = gc >> 6, col = gc & 63;
                if (m < 2) {
                    uint32_t* dst = sm + (m == 0 ? W_K : W_Q);
                    dst[r0 * LDH + (col >> 1)] = pkh2(c[mt][nt][0], c[mt][nt][1]);
                    dst[r1 * LDH + (col >> 1)] = pkh2(c[mt][nt][2], c[mt][nt][3]);
                } else {
                    vh[(col    ) * (LDVT * 2) + r0] = __float2half_rn(c[mt][nt][0]);
                    vh[(col + 1) * (LDVT * 2) + r0] = __float2half_rn(c[mt][nt][1]);
                    vh[(col    ) * (LDVT * 2) + r1] = __float2half_rn(c[mt][nt][2]);
                    vh[(col + 1) * (LDVT * 2) + r1] = __float2half_rn(c[mt][nt][3]);
                }
            }
        }
    }
    __syncthreads();

    // ===== Stage B: S = scale * Q @ K^T  (M=128,N=128,K=64) =====
    {
        float cs[2][4][4];
#pragma unroll
        for (int mt = 0; mt < 2; ++mt)
#pragma unroll
            for (int nt = 0; nt < 4; ++nt)
#pragma unroll
                for (int j = 0; j < 4; ++j) cs[mt][nt][j] = 0.f;
        const uint32_t* sQ = sm + W_Q;
        const uint32_t* sK = sm + W_K;
#pragma unroll
        for (int kk = 0; kk < 4; ++kk) {
            uint32_t a[2][4];
#pragma unroll
            for (int mt = 0; mt < 2; ++mt) {
                int r0 = wm * 32 + mt * 16 + g4;
                a[mt][0] = sQ[(r0    ) * LDH + kk * 8 + t4];
                a[mt][1] = sQ[(r0 + 8) * LDH + kk * 8 + t4];
                a[mt][2] = sQ[(r0    ) * LDH + kk * 8 + t4 + 4];
                a[mt][3] = sQ[(r0 + 8) * LDH + kk * 8 + t4 + 4];
            }
#pragma unroll
            for (int nt = 0; nt < 4; ++nt) {
                int n = wn * 32 + nt * 8 + g4;
                uint32_t b0 = sK[n * LDH + kk * 8 + t4];
                uint32_t b1 = sK[n * LDH + kk * 8 + t4 + 4];
                mma_f16(cs[0][nt], a[0], b0, b1);
                mma_f16(cs[1][nt], a[1], b0, b1);
            }
        }
        const float scale = 0.05103103630798288f;    // 384^-0.5
        float* sS = (float*)(sm + W_S);
#pragma unroll
        for (int mt = 0; mt < 2; ++mt) {
            int r0 = wm * 32 + mt * 16 + g4, r1 = r0 + 8;
#pragma unroll
            for (int nt = 0; nt < 4; ++nt) {
                int gc = wn * 32 + nt * 8 + 2 * t4;
                *(float2*)(sS + r0 * LDS_ + gc) =
                    make_float2(cs[mt][nt][0] * scale, cs[mt][nt][1] * scale);
                *(float2*)(sS + r1 * LDS_ + gc) =
                    make_float2(cs[mt][nt][2] * scale, cs[mt][nt][3] * scale);
            }
        }
    }
    __syncthreads();

    // ===== Stage C: causal softmax; P packed to half2 =====
    if (tid < kT) {
        const int t = tid;
        const float* rowf = (const float*)(sm + W_S) + t * LDS_;
        uint32_t* rowp = sm + W_P + t * LDP;
        float m = -1e30f;
        for (int s = 0; s <= t; ++s) m = fmaxf(m, rowf[s]);
        float sum = 0.f;
        float e[kT];
        for (int s = 0; s <= t; ++s) {
            e[s] = __expf(rowf[s] - m);
            sum += e[s];
        }
        const float inv = 1.0f / sum;
        for (int s2 = 0; s2 < kT / 2; ++s2) {
            float p0 = (2 * s2     <= t) ? e[2 * s2]     * inv : 0.f;
            float p1 = (2 * s2 + 1 <= t) ? e[2 * s2 + 1] * inv : 0.f;
            rowp[s2] = pkh2(p0, p1);
        }
    }
    __syncthreads();

    // ===== Stage D: out = P @ V  (M=128,N=64,K=128) =====
    {
        float co[2][2][4];
#pragma unroll
        for (int mt = 0; mt < 2; ++mt)
#pragma unroll
            for (int nt = 0; nt < 2; ++nt)
#pragma unroll
                for (int j = 0; j < 4; ++j) co[mt][nt][j] = 0.f;
        const uint32_t* sP = sm + W_P;
        const uint32_t* sVt = sm + W_VT;
#pragma unroll
        for (int kk = 0; kk < 8; ++kk) {
            uint32_t a[2][4];
#pragma unroll
            for (int mt = 0; mt < 2; ++mt) {
                int r0 = wm * 32 + mt * 16 + g4;
                a[mt][0] = sP[(r0    ) * LDP + kk * 8 + t4];
                a[mt][1] = sP[(r0 + 8) * LDP + kk * 8 + t4];
                a[mt][2] = sP[(r0    ) * LDP + kk * 8 + t4 + 4];
                a[mt][3] = sP[(r0 + 8) * LDP + kk * 8 + t4 + 4];
            }
#pragma unroll
            for (int nt = 0; nt < 2; ++nt) {
                int h = wn * 16 + nt * 8 + g4;
                uint32_t b0 = sVt[h * LDVT + kk * 8 + t4];
                uint32_t b1 = sVt[h * LDVT + kk * 8 + t4 + 4];
                mma_f16(co[0][nt], a[0], b0, b1);
                mma_f16(co[1][nt], a[1], b0, b1);
            }
        }
        float* ob = out + (size_t)b * (kT * kHS);
#pragma unroll
        for (int mt = 0; mt < 2; ++mt) {
            int r0 = wm * 32 + mt * 16 + g4, r1 = r0 + 8;
#pragma unroll
            for (int nt = 0; nt < 2; ++nt) {
                int h0 = wn * 16 + nt * 8 + 2 * t4;
                *(float2*)(ob + r0 * kHS + h0) = make_float2(co[mt][nt][0], co[mt][nt][1]);
                *(float2*)(ob + r1 * kHS + h0) = make_float2(co[mt][nt][2], co[mt][nt][3]);
            }
        }
    }
}

extern "C" void kernel_launch(void* const* d_in, const int* in_sizes, int n_in,
                              void* d_out, int out_size) {
    const float* x  = (const float*)d_in[0];
    const float* Wk = (const float*)d_in[1];
    const float* Wq = (const float*)d_in[2];
    const float* Wv = (const float*)d_in[3];
    float* out = (float*)d_out;

    const int B = in_sizes[0] / (kT * kC);   // 1024
    cudaFuncSetAttribute(attn_mma_kernel,
                         cudaFuncAttributeMaxDynamicSharedMemorySize, SMEM_BYTES);
    attn_mma_kernel<<<B, 512, SMEM_BYTES>>>(x, Wk, Wq, Wv, out);
}

// round 7
// speedup vs baseline: 4.6043x; 1.1298x over previous
#include <cuda_runtime.h>
#include <cuda_fp16.h>
#include <cstdint>

// Fused causal self-attention head, mma.sync m16n8k16 fp16 (fp32 accum) + ldmatrix.
// B=1024, T=128, C=384, HS=64, fp32 in/out.
// One CTA per batch, 512 threads (16 warps), ~154KB dynamic smem.

static constexpr int kT   = 128;
static constexpr int kC   = 384;
static constexpr int kHS  = 64;
static constexpr int kCH  = 32;             // K-chunk (floats)
static constexpr int kNCH = kC / kCH;       // 12
static constexpr int kNW  = 192;            // combined N = 3*64 (Wk|Wq|Wv)

// strides in 4B words (half2 units for fp16 regions)
static constexpr int LDXW = 20;             // x/w staging rows: 16 half2 data + 4 pad
static constexpr int LDH  = 36;             // K/Q rows: 32 half2 + 4 pad
static constexpr int LDVT = 68;             // Vt rows: 64 half2 + 4 pad
static constexpr int LDS_ = 134;            // S rows (fp32 words)
static constexpr int LDP  = 68;             // P rows: 64 half2 + 4 pad

static constexpr int W_K  = 0;
static constexpr int W_Q  = W_K + kT * LDH;         // 4608
static constexpr int W_VT = W_Q + kT * LDH;         // 9216
static constexpr int W_U  = W_VT + kHS * LDVT;      // 13568
static constexpr int XBUF_W = kT  * LDXW;           // 2560
static constexpr int WBUF_W = kNW * LDXW;           // 3840
static constexpr int BUF_W  = XBUF_W + WBUF_W;      // 6400 (2 bufs alias S/P region)
static constexpr int W_S  = W_U;                    // fp32 scores
static constexpr int W_P  = W_S + kT * LDS_;        // 30720
static constexpr int SMEM_WORDS = W_P + kT * LDP;   // 39424
static constexpr int SMEM_BYTES = SMEM_WORDS * 4;   // 157696

// ---------------- helpers ----------------
__device__ __forceinline__ uint32_t pkh2(float a, float b) {
    __half2 h = __floats2half2_rn(a, b);
    return *(uint32_t*)&h;
}
__device__ __forceinline__ uint32_t s2u(const void* p) {
    uint32_t a;
    asm("{ .reg .u64 t; cvta.to.shared.u64 t, %1; cvt.u32.u64 %0, t; }" : "=r"(a) : "l"(p));
    return a;
}
__device__ __forceinline__ void mma_f16(float c[4], const uint32_t a[4],
                                        uint32_t b0, uint32_t b1) {
    asm volatile(
        "mma.sync.aligned.m16n8k16.row.col.f32.f16.f16.f32 "
        "{%0,%1,%2,%3}, {%4,%5,%6,%7}, {%8,%9}, {%0,%1,%2,%3};"
        : "+f"(c[0]), "+f"(c[1]), "+f"(c[2]), "+f"(c[3])
        : "r"(a[0]), "r"(a[1]), "r"(a[2]), "r"(a[3]), "r"(b0), "r"(b1));
}
__device__ __forceinline__ void ldmx4(uint32_t& r0, uint32_t& r1,
                                      uint32_t& r2, uint32_t& r3, uint32_t addr) {
    asm volatile("ldmatrix.sync.aligned.m8n8.x4.shared.b16 {%0,%1,%2,%3}, [%4];"
                 : "=r"(r0), "=r"(r1), "=r"(r2), "=r"(r3) : "r"(addr));
}

// ---------------- kernel ----------------
__global__ void __launch_bounds__(512, 1)
attn_mma_kernel(const float* __restrict__ x,
                const float* __restrict__ Wk,
                const float* __restrict__ Wq,
                const float* __restrict__ Wv,
                float* __restrict__ out) {
    extern __shared__ uint32_t sm[];
    const uint32_t smu = s2u(sm);
    const int tid  = threadIdx.x;
    const int wid  = tid >> 5;
    const int lane = tid & 31;
    const int g4   = lane >> 2;      // 0..7
    const int t4   = lane & 3;       // 0..3
    const int wm   = wid & 3;        // m-group (32 rows)
    const int wn   = wid >> 2;       // n-group
    const int l15  = lane & 15;      // ldmatrix row select
    const int l16w = (lane >> 4) * 4; // ldmatrix col-half select (words)
    const int b    = blockIdx.x;
    const float* xb = x + (size_t)b * (kT * kC);

    // ===== Stage A: KQV = x @ [Wk|Wq|Wv]^T, K-chunked, reg-prefetch dbuf =====
    float4 xr[2], wr[3];
    {
#pragma unroll
        for (int r = 0; r < 2; ++r) {
            int idx = tid + 512 * r, t = idx >> 3, f4 = idx & 7;
            xr[r] = *(const float4*)(xb + t * kC + f4 * 4);
        }
#pragma unroll
        for (int r = 0; r < 3; ++r) {
            int idx = tid + 512 * r, n = idx >> 3, f4 = idx & 7;
            const float* Wm = (n < 64) ? (Wk + n * kC)
                              : (n < 128) ? (Wq + (n - 64) * kC)
                                          : (Wv + (n - 128) * kC);
            wr[r] = *(const float4*)(Wm + f4 * 4);
        }
    }
    {
        uint32_t* bx = sm + W_U;
        uint32_t* bw = bx + XBUF_W;
#pragma unroll
        for (int r = 0; r < 2; ++r) {
            int idx = tid + 512 * r, t = idx >> 3, f4 = idx & 7;
            *(uint2*)(bx + t * LDXW + f4 * 2) =
                make_uint2(pkh2(xr[r].x, xr[r].y), pkh2(xr[r].z, xr[r].w));
        }
#pragma unroll
        for (int r = 0; r < 3; ++r) {
            int idx = tid + 512 * r, n = idx >> 3, f4 = idx & 7;
            *(uint2*)(bw + n * LDXW + f4 * 2) =
                make_uint2(pkh2(wr[r].x, wr[r].y), pkh2(wr[r].z, wr[r].w));
        }
    }
    __syncthreads();

    float c[2][6][4];
#pragma unroll
    for (int mt = 0; mt < 2; ++mt)
#pragma unroll
        for (int nt = 0; nt < 6; ++nt)
#pragma unroll
            for (int j = 0; j < 4; ++j) c[mt][nt][j] = 0.f;

    for (int cb = 0; cb < kNCH; ++cb) {
        const int p = cb & 1;
        if (cb + 1 < kNCH) {
            const int cbase = (cb + 1) * kCH;
#pragma unroll
            for (int r = 0; r < 2; ++r) {
                int idx = tid + 512 * r, t = idx >> 3, f4 = idx & 7;
                xr[r] = *(const float4*)(xb + t * kC + cbase + f4 * 4);
            }
#pragma unroll
            for (int r = 0; r < 3; ++r) {
                int idx = tid + 512 * r, n = idx >> 3, f4 = idx & 7;
                const float* Wm = (n < 64) ? (Wk + n * kC)
                                  : (n < 128) ? (Wq + (n - 64) * kC)
                                              : (Wv + (n - 128) * kC);
                wr[r] = *(const float4*)(Wm + cbase + f4 * 4);
            }
        }
        {
            const uint32_t bx = smu + 4 * (uint32_t)(W_U + p * BUF_W);
            const uint32_t bw = bx + 4 * (uint32_t)XBUF_W;
#pragma unroll
            for (int kk = 0; kk < 2; ++kk) {
                uint32_t a[2][4];
#pragma unroll
                for (int mt = 0; mt < 2; ++mt)
                    ldmx4(a[mt][0], a[mt][1], a[mt][2], a[mt][3],
                          bx + 4 * ((wm * 32 + mt * 16 + l15) * LDXW + kk * 8 + l16w));
#pragma unroll
                for (int np = 0; np < 3; ++np) {
                    uint32_t r0, r1, r2, r3;
                    ldmx4(r0, r1, r2, r3,
                          bw + 4 * ((wn * 48 + np * 16 + l15) * LDXW + kk * 8 + l16w));
                    mma_f16(c[0][2 * np    ], a[0], r0, r2);
                    mma_f16(c[1][2 * np    ], a[1], r0, r2);
                    mma_f16(c[0][2 * np + 1], a[0], r1, r3);
                    mma_f16(c[1][2 * np + 1], a[1], r1, r3);
                }
            }
        }
        if (cb + 1 < kNCH) {
            uint32_t* bx = sm + W_U + (p ^ 1) * BUF_W;
            uint32_t* bw = bx + XBUF_W;
#pragma unroll
            for (int r = 0; r < 2; ++r) {
                int idx = tid + 512 * r, t = idx >> 3, f4 = idx & 7;
                *(uint2*)(bx + t * LDXW + f4 * 2) =
                    make_uint2(pkh2(xr[r].x, xr[r].y), pkh2(xr[r].z, xr[r].w));
            }
#pragma unroll
            for (int r = 0; r < 3; ++r) {
                int idx = tid + 512 * r, n = idx >> 3, f4 = idx & 7;
                *(uint2*)(bw + n * LDXW + f4 * 2) =
                    make_uint2(pkh2(wr[r].x, wr[r].y), pkh2(wr[r].z, wr[r].w));
            }
        }
        __syncthreads();
    }

    // epilogue: K,Q row-major half2 [t][h]; V transposed half [h][s]
    {
        __half* vh = (__half*)(sm + W_VT);
#pragma unroll
        for (int mt = 0; mt < 2; ++mt) {
            int r0 = wm * 32 + mt * 16 + g4, r1 = r0 + 8;
#pragma unroll
            for (int nt = 0; nt < 6; ++nt) {
                int gc = wn * 48 + nt * 8 + 2 * t4;
                int m = gc >> 6, col = gc & 63;
                if (m < 2) {
                    uint32_t* dst = sm + (m == 0 ? W_K : W_Q);
                    dst[r0 * LDH + (col >> 1)] = pkh2(c[mt][nt][0], c[mt][nt][1]);
                    dst[r1 * LDH + (col >> 1)] = pkh2(c[mt][nt][2], c[mt][nt][3]);
                } else {
                    vh[(col    ) * (LDVT * 2) + r0] = __float2half_rn(c[mt][nt][0]);
                    vh[(col + 1) * (LDVT * 2) + r0] = __float2half_rn(c[mt][nt][1]);
                    vh[(col    ) * (LDVT * 2) + r1] = __float2half_rn(c[mt][nt][2]);
                    vh[(col + 1) * (LDVT * 2) + r1] = __float2half_rn(c[mt][nt][3]);
                }
            }
        }
    }
    __syncthreads();

    // ===== Stage B: S = scale * Q @ K^T  (M=128,N=128,K=64) =====
    {
        float cs[2][4][4];
#pragma unroll
        for (int mt = 0; mt < 2; ++mt)
#pragma unroll
            for (int nt = 0; nt < 4; ++nt)
#pragma unroll
                for (int j = 0; j < 4; ++j) cs[mt][nt][j] = 0.f;
#pragma unroll
        for (int kk = 0; kk < 4; ++kk) {
            uint32_t a[2][4];
#pragma unroll
            for (int mt = 0; mt < 2; ++mt)
                ldmx4(a[mt][0], a[mt][1], a[mt][2], a[mt][3],
                      smu + 4 * (W_Q + (wm * 32 + mt * 16 + l15) * LDH + kk * 8 + l16w));
#pragma unroll
            for (int np = 0; np < 2; ++np) {
                uint32_t r0, r1, r2, r3;
                ldmx4(r0, r1, r2, r3,
                      smu + 4 * (W_K + (wn * 32 + np * 16 + l15) * LDH + kk * 8 + l16w));
                mma_f16(cs[0][2 * np    ], a[0], r0, r2);
                mma_f16(cs[1][2 * np    ], a[1], r0, r2);
                mma_f16(cs[0][2 * np + 1], a[0], r1, r3);
                mma_f16(cs[1][2 * np + 1], a[1], r1, r3);
            }
        }
        const float scale = 0.05103103630798288f;    // 384^-0.5
        float* sS = (float*)(sm + W_S);
#pragma unroll
        for (int mt = 0; mt < 2; ++mt) {
            int r0 = wm * 32 + mt * 16 + g4, r1 = r0 + 8;
#pragma unroll
            for (int nt = 0; nt < 4; ++nt) {
                int gc = wn * 32 + nt * 8 + 2 * t4;
                *(float2*)(sS + r0 * LDS_ + gc) =
                    make_float2(cs[mt][nt][0] * scale, cs[mt][nt][1] * scale);
                *(float2*)(sS + r1 * LDS_ + gc) =
                    make_float2(cs[mt][nt][2] * scale, cs[mt][nt][3] * scale);
            }
        }
    }
    __syncthreads();

    // ===== Stage C: causal softmax; 4 threads per row; P packed half2 =====
    {
        const int row = tid >> 2;     // 0..127
        const int sub = tid & 3;      // 0..3, covers cols [sub*32, sub*32+32)
        const float* rowf = (const float*)(sm + W_S) + row * LDS_ + sub * 32;
        float v[32];
        float m = -1e30f;
#pragma unroll
        for (int j = 0; j < 32; ++j) {
            int col = sub * 32 + j;
            float f = (col <= row) ? rowf[j] : -1e30f;
            v[j] = f;
            m = fmaxf(m, f);
        }
        m = fmaxf(m, __shfl_xor_sync(0xffffffffu, m, 1));
        m = fmaxf(m, __shfl_xor_sync(0xffffffffu, m, 2));
        float s = 0.f;
#pragma unroll
        for (int j = 0; j < 32; ++j) {
            v[j] = __expf(v[j] - m);
            s += v[j];
        }
        s += __shfl_xor_sync(0xffffffffu, s, 1);
        s += __shfl_xor_sync(0xffffffffu, s, 2);
        const float inv = 1.0f / s;
        uint32_t* rowp = sm + W_P + row * LDP + sub * 16;
#pragma unroll
        for (int j = 0; j < 16; ++j)
            rowp[j] = pkh2(v[2 * j] * inv, v[2 * j + 1] * inv);
    }
    __syncthreads();

    // ===== Stage D: out = P @ V  (M=128,N=64,K=128) =====
    {
        float co[2][2][4];
#pragma unroll
        for (int mt = 0; mt < 2; ++mt)
#pragma unroll
            for (int nt = 0; nt < 2; ++nt)
#pragma unroll
                for (int j = 0; j < 4; ++j) co[mt][nt][j] = 0.f;
#pragma unroll
        for (int kk = 0; kk < 8; ++kk) {
            uint32_t a[2][4];
#pragma unroll
            for (int mt = 0; mt < 2; ++mt)
                ldmx4(a[mt][0], a[mt][1], a[mt][2], a[mt][3],
                      smu + 4 * (W_P + (wm * 32 + mt * 16 + l15) * LDP + kk * 8 + l16w));
            uint32_t r0, r1, r2, r3;
            ldmx4(r0, r1, r2, r3,
                  smu + 4 * (W_VT + (wn * 16 + l15) * LDVT + kk * 8 + l16w));
            mma_f16(co[0][0], a[0], r0, r2);
            mma_f16(co[1][0], a[1], r0, r2);
            mma_f16(co[0][1], a[0], r1, r3);
            mma_f16(co[1][1], a[1], r1, r3);
        }
        float* ob = out + (size_t)b * (kT * kHS);
#pragma unroll
        for (int mt = 0; mt < 2; ++mt) {
            int r0 = wm * 32 + mt * 16 + g4, r1 = r0 + 8;
#pragma unroll
            for (int nt = 0; nt < 2; ++nt) {
                int h0 = wn * 16 + nt * 8 + 2 * t4;
                *(float2*)(ob + r0 * kHS + h0) = make_float2(co[mt][nt][0], co[mt][nt][1]);
                *(float2*)(ob + r1 * kHS + h0) = make_float2(co[mt][nt][2], co[mt][nt][3]);
            }
        }
    }
}

extern "C" void kernel_launch(void* const* d_in, const int* in_sizes, int n_in,
                              void* d_out, int out_size) {
    const float* x  = (const float*)d_in[0];
    const float* Wk = (const float*)d_in[1];
    const float* Wq = (const float*)d_in[2];
    const float* Wv = (const float*)d_in[3];
    float* out = (float*)d_out;

    const int B = in_sizes[0] / (kT * kC);   // 1024
    cudaFuncSetAttribute(attn_mma_kernel,
                         cudaFuncAttributeMaxDynamicSharedMemorySize, SMEM_BYTES);
    attn_mma_kernel<<<B, 512, SMEM_BYTES>>>(x, Wk, Wq, Wv, out);
}